// round 2
// baseline (speedup 1.0000x reference)
#include <cuda_runtime.h>
#include <math.h>

#define Tdim 4096
#define Hdim 4096
#define Idim 11008
#define KH4 (Hdim/4)   // 1024 int32 per row
#define KI4 (Idim/4)   // 2752 int32 per row
#define NWELEM ((size_t)Idim*(size_t)Hdim)  // 45,088,768 (same for all 3 weights)

// ---- static device scratch (no cudaMalloc allowed) ----
__device__ __align__(16) signed char g_wq_gate[NWELEM];
__device__ __align__(16) signed char g_wq_up[NWELEM];
__device__ __align__(16) signed char g_wq_down[NWELEM];
__device__ __align__(16) signed char g_xq[(size_t)Tdim*Hdim];
__device__ __align__(16) signed char g_hq[(size_t)Tdim*Idim];
__device__ float g_gbuf[(size_t)Tdim*Idim];     // gate out, then h=silu(g)*u in place
__device__ float g_ainv[Tdim];
__device__ float g_hinv[Tdim];
__device__ float g_partial[3][2048];
__device__ float g_wscale[3];  // sw = 1/clip(mean|w|,1e-5)
__device__ float g_winv[3];    // 1/sw

// ---------------- absmean reduction (two-pass, deterministic) ----------------
__global__ void absmean_partial(const float* __restrict__ w, long n, int which) {
    __shared__ float red[256];
    float s = 0.f;
    long stride = (long)gridDim.x * blockDim.x;
    for (long i = (long)blockIdx.x * blockDim.x + threadIdx.x; i < n; i += stride)
        s += fabsf(w[i]);
    red[threadIdx.x] = s;
    __syncthreads();
    for (int o = 128; o > 0; o >>= 1) {
        if (threadIdx.x < o) red[threadIdx.x] += red[threadIdx.x + o];
        __syncthreads();
    }
    if (threadIdx.x == 0) g_partial[which][blockIdx.x] = red[0];
}

__global__ void finalize_scales(long n) {
    if (threadIdx.x == 0 && blockIdx.x == 0) {
        for (int w = 0; w < 3; w++) {
            double s = 0.0;
            for (int i = 0; i < 2048; i++) s += (double)g_partial[w][i];
            float mean = (float)(s / (double)n);
            float cm = fmaxf(mean, 1e-5f);
            g_wscale[w] = 1.f / cm;
            g_winv[w] = cm;
        }
    }
}

// ---------------- weight ternary quantization ----------------
__global__ void quant_weight(const float* __restrict__ w, signed char* __restrict__ wq,
                             long n, int which) {
    float sw = g_wscale[which];
    long stride = (long)gridDim.x * blockDim.x * 4;
    for (long i = ((long)blockIdx.x * blockDim.x + threadIdx.x) * 4; i < n; i += stride) {
        float4 v = *(const float4*)(w + i);
        char4 q;
        q.x = (signed char)fminf(1.f, fmaxf(-1.f, rintf(v.x * sw)));
        q.y = (signed char)fminf(1.f, fmaxf(-1.f, rintf(v.y * sw)));
        q.z = (signed char)fminf(1.f, fmaxf(-1.f, rintf(v.z * sw)));
        q.w = (signed char)fminf(1.f, fmaxf(-1.f, rintf(v.w * sw)));
        *(char4*)(wq + i) = q;
    }
}

// ---------------- per-token activation quantization (x input) ----------------
__global__ void quant_act(const float* __restrict__ x, signed char* __restrict__ xq,
                          float* __restrict__ ainv, int ncols) {
    __shared__ float red[256];
    int tid = threadIdx.x;
    long base = (long)blockIdx.x * ncols;
    float mx = 0.f;
    for (int i = tid; i < ncols; i += 256) mx = fmaxf(mx, fabsf(x[base + i]));
    red[tid] = mx;
    __syncthreads();
    for (int o = 128; o > 0; o >>= 1) {
        if (tid < o) red[tid] = fmaxf(red[tid], red[tid + o]);
        __syncthreads();
    }
    float cm = fmaxf(red[0], 1e-5f);
    float s = 127.f / cm;
    if (tid == 0) ainv[blockIdx.x] = cm * (1.f / 127.f);
    for (int i = tid; i < ncols; i += 256) {
        float v = rintf(x[base + i] * s);
        v = fminf(127.f, fmaxf(-128.f, v));
        xq[base + i] = (signed char)v;
    }
}

// ---------------- fused rmsnorm + per-token act quant on h [T, I] ----------------
__global__ void rmsnorm_quant(const float* __restrict__ h, const float* __restrict__ lnw,
                              signed char* __restrict__ hq, float* __restrict__ hinv) {
    __shared__ float sh[Idim];   // 44032 B
    __shared__ float red[256];
    int tid = threadIdx.x;
    long base = (long)blockIdx.x * Idim;
    float ss = 0.f;
    for (int i = tid; i < Idim; i += 256) {
        float v = h[base + i];
        sh[i] = v;
        ss += v * v;
    }
    red[tid] = ss;
    __syncthreads();
    for (int o = 128; o > 0; o >>= 1) {
        if (tid < o) red[tid] += red[tid + o];
        __syncthreads();
    }
    float rs = rsqrtf(red[0] / (float)Idim + 1e-6f);
    __syncthreads();
    float mx = 0.f;
    for (int i = tid; i < Idim; i += 256) {
        float hn = lnw[i] * sh[i] * rs;
        sh[i] = hn;
        mx = fmaxf(mx, fabsf(hn));
    }
    red[tid] = mx;
    __syncthreads();
    for (int o = 128; o > 0; o >>= 1) {
        if (tid < o) red[tid] = fmaxf(red[tid], red[tid + o]);
        __syncthreads();
    }
    float cm = fmaxf(red[0], 1e-5f);
    float s = 127.f / cm;
    if (tid == 0) hinv[blockIdx.x] = cm * (1.f / 127.f);
    for (int i = tid; i < Idim; i += 256) {
        float v = rintf(sh[i] * s);
        v = fminf(127.f, fmaxf(-128.f, v));
        hq[base + i] = (signed char)v;
    }
}

// ---------------- int8 dp4a GEMM: C[m,n] = scale * sum_k A[m,k]*B[n,k] ----------------
// A: [M, K4] int32 (packed int8), B: [N, K4] int32, K4 % 16 == 0, M,N % 128 == 0.
// SILU=1: epilogue reads C (gate output g) and writes silu(g)*val in place.
template<int SILU>
__global__ void __launch_bounds__(256, 2)
gemm_i8(const signed char* __restrict__ A8, const signed char* __restrict__ B8,
        float* __restrict__ C, int N, int K4,
        const float* __restrict__ rowinv, int widx)
{
    __shared__ int As[16][132];
    __shared__ int Bs[16][132];
    const int* A = (const int*)A8;
    const int* B = (const int*)B8;
    int tid = threadIdx.x;
    int tx = tid & 15, ty = tid >> 4;
    int m0 = blockIdx.y * 128, n0 = blockIdx.x * 128;

    int acc[8][8];
#pragma unroll
    for (int i = 0; i < 8; i++)
#pragma unroll
        for (int j = 0; j < 8; j++) acc[i][j] = 0;

    int lrow = tid >> 2;          // 0..63
    int kc = (tid & 3) * 4;       // 0,4,8,12
    const int* Ag0 = A + (long)(m0 + lrow) * K4 + kc;
    const int* Ag1 = Ag0 + (long)64 * K4;
    const int* Bg0 = B + (long)(n0 + lrow) * K4 + kc;
    const int* Bg1 = Bg0 + (long)64 * K4;

    int nk = K4 / 16;
    for (int kt = 0; kt < nk; kt++) {
        int kb = kt * 16;
        int4 a0 = *(const int4*)(Ag0 + kb);
        int4 a1 = *(const int4*)(Ag1 + kb);
        int4 b0 = *(const int4*)(Bg0 + kb);
        int4 b1 = *(const int4*)(Bg1 + kb);

        As[kc + 0][lrow] = a0.x; As[kc + 1][lrow] = a0.y;
        As[kc + 2][lrow] = a0.z; As[kc + 3][lrow] = a0.w;
        As[kc + 0][lrow + 64] = a1.x; As[kc + 1][lrow + 64] = a1.y;
        As[kc + 2][lrow + 64] = a1.z; As[kc + 3][lrow + 64] = a1.w;
        Bs[kc + 0][lrow] = b0.x; Bs[kc + 1][lrow] = b0.y;
        Bs[kc + 2][lrow] = b0.z; Bs[kc + 3][lrow] = b0.w;
        Bs[kc + 0][lrow + 64] = b1.x; Bs[kc + 1][lrow + 64] = b1.y;
        Bs[kc + 2][lrow + 64] = b1.z; Bs[kc + 3][lrow + 64] = b1.w;
        __syncthreads();

#pragma unroll
        for (int kk = 0; kk < 16; kk++) {
            int a[8], b[8];
            *(int4*)(a)     = *(const int4*)(&As[kk][ty * 8]);
            *(int4*)(a + 4) = *(const int4*)(&As[kk][ty * 8 + 4]);
            *(int4*)(b)     = *(const int4*)(&Bs[kk][tx * 8]);
            *(int4*)(b + 4) = *(const int4*)(&Bs[kk][tx * 8 + 4]);
#pragma unroll
            for (int i = 0; i < 8; i++)
#pragma unroll
                for (int j = 0; j < 8; j++)
                    acc[i][j] = __dp4a(a[i], b[j], acc[i][j]);
        }
        __syncthreads();
    }

    float winv = g_winv[widx];
#pragma unroll
    for (int i = 0; i < 8; i++) {
        int m = m0 + ty * 8 + i;
        float rsc = rowinv[m] * winv;
#pragma unroll
        for (int j = 0; j < 8; j++) {
            long idx = (long)m * N + n0 + tx * 8 + j;
            float v = (float)acc[i][j] * rsc;
            if (SILU) {
                float g = C[idx];
                C[idx] = (g / (1.f + expf(-g))) * v;
            } else {
                C[idx] = v;
            }
        }
    }
}

extern "C" void kernel_launch(void* const* d_in, const int* in_sizes, int n_in,
                              void* d_out, int out_size) {
    const float* x   = (const float*)d_in[0];
    const float* wg  = (const float*)d_in[1];
    const float* wu  = (const float*)d_in[2];
    const float* wd  = (const float*)d_in[3];
    const float* lnw = (const float*)d_in[4];
    float* out = (float*)d_out;

    signed char *wq_gate, *wq_up, *wq_down, *xq, *hq;
    float *gbuf, *ainv, *hinv;
    cudaGetSymbolAddress((void**)&wq_gate, g_wq_gate);
    cudaGetSymbolAddress((void**)&wq_up, g_wq_up);
    cudaGetSymbolAddress((void**)&wq_down, g_wq_down);
    cudaGetSymbolAddress((void**)&xq, g_xq);
    cudaGetSymbolAddress((void**)&hq, g_hq);
    cudaGetSymbolAddress((void**)&gbuf, g_gbuf);
    cudaGetSymbolAddress((void**)&ainv, g_ainv);
    cudaGetSymbolAddress((void**)&hinv, g_hinv);

    const long NW = (long)NWELEM;

    absmean_partial<<<2048, 256>>>(wg, NW, 0);
    absmean_partial<<<2048, 256>>>(wu, NW, 1);
    absmean_partial<<<2048, 256>>>(wd, NW, 2);
    finalize_scales<<<1, 32>>>(NW);

    quant_weight<<<4096, 256>>>(wg, wq_gate, NW, 0);
    quant_weight<<<4096, 256>>>(wu, wq_up, NW, 1);
    quant_weight<<<4096, 256>>>(wd, wq_down, NW, 2);

    quant_act<<<Tdim, 256>>>(x, xq, ainv, Hdim);

    dim3 g1(Idim / 128, Tdim / 128);   // (86, 32)
    gemm_i8<0><<<g1, 256>>>(xq, wq_gate, gbuf, Idim, KH4, ainv, 0);
    gemm_i8<1><<<g1, 256>>>(xq, wq_up, gbuf, Idim, KH4, ainv, 1);

    rmsnorm_quant<<<Tdim, 256>>>(gbuf, lnw, hq, hinv);

    dim3 g2(Hdim / 128, Tdim / 128);   // (32, 32)
    gemm_i8<0><<<g2, 256>>>(hq, wq_down, out, Hdim, KI4, hinv, 2);
}

// round 4
// speedup vs baseline: 1.1425x; 1.1425x over previous
#include <cuda_runtime.h>
#include <math.h>
#include <stdint.h>

#define Tdim 4096
#define Hdim 4096
#define Idim 11008
#define NW ((size_t)Idim*(size_t)Hdim)

// ---- static device scratch (no cudaMalloc allowed) ----
__device__ __align__(16) signed char g_wqg[NW];
__device__ __align__(16) signed char g_wqu[NW];
__device__ __align__(16) signed char g_wqd[NW];
__device__ __align__(16) signed char g_xq[(size_t)Tdim*Hdim];
__device__ __align__(16) signed char g_hq[(size_t)Tdim*Idim];
__device__ float g_gbuf[(size_t)Tdim*Idim];
__device__ float g_ainv[Tdim];
__device__ float g_hinv[Tdim];
__device__ float g_partial[3][2048];
__device__ float g_wscale[3];
__device__ float g_winv[3];

// ======================= PTX helpers =======================
__device__ __forceinline__ uint32_t smem_u32(const void* p) {
    uint32_t a;
    asm("{ .reg .u64 t; cvta.to.shared.u64 t, %1; cvt.u32.u64 %0, t; }" : "=r"(a) : "l"(p));
    return a;
}
__device__ __forceinline__ void cp16(uint32_t dst, const void* src) {
    asm volatile("cp.async.cg.shared.global [%0], [%1], 16;" :: "r"(dst), "l"(src));
}
#define CP_COMMIT() asm volatile("cp.async.commit_group;" ::: "memory")
template<int N> __device__ __forceinline__ void cp_wait() {
    asm volatile("cp.async.wait_group %0;" :: "n"(N) : "memory");
}
#define LDSM4(r, a) asm volatile( \
    "ldmatrix.sync.aligned.m8n8.x4.shared.b16 {%0,%1,%2,%3}, [%4];" \
    : "=r"((r)[0]), "=r"((r)[1]), "=r"((r)[2]), "=r"((r)[3]) : "r"(a))
#define MMA_S8(d, a, b0, b1) asm volatile( \
    "mma.sync.aligned.m16n8k32.row.col.s32.s8.s8.s32 " \
    "{%0,%1,%2,%3}, {%4,%5,%6,%7}, {%8,%9}, {%0,%1,%2,%3};" \
    : "+r"((d)[0]), "+r"((d)[1]), "+r"((d)[2]), "+r"((d)[3]) \
    : "r"((a)[0]), "r"((a)[1]), "r"((a)[2]), "r"((a)[3]), "r"(b0), "r"(b1))

// ======================= aux kernels =======================
__global__ void absmean_partial(const float* __restrict__ w, long n, int which) {
    __shared__ float red[256];
    float s = 0.f;
    long stride = (long)gridDim.x * blockDim.x;
    for (long i = (long)blockIdx.x * blockDim.x + threadIdx.x; i < n; i += stride)
        s += fabsf(w[i]);
    red[threadIdx.x] = s;
    __syncthreads();
    for (int o = 128; o > 0; o >>= 1) {
        if (threadIdx.x < o) red[threadIdx.x] += red[threadIdx.x + o];
        __syncthreads();
    }
    if (threadIdx.x == 0) g_partial[which][blockIdx.x] = red[0];
}

__global__ void finalize_scales(long n) {
    __shared__ double red[256];
    int w = blockIdx.x;
    double s = 0.0;
    for (int i = threadIdx.x; i < 2048; i += 256) s += (double)g_partial[w][i];
    red[threadIdx.x] = s;
    __syncthreads();
    for (int o = 128; o > 0; o >>= 1) {
        if (threadIdx.x < o) red[threadIdx.x] += red[threadIdx.x + o];
        __syncthreads();
    }
    if (threadIdx.x == 0) {
        float mean = (float)(red[0] / (double)n);
        float cm = fmaxf(mean, 1e-5f);
        g_wscale[w] = 1.f / cm;
        g_winv[w] = cm;
    }
}

__global__ void quant_weight(const float* __restrict__ w, signed char* __restrict__ wq,
                             long n, int which) {
    float sw = g_wscale[which];
    long stride = (long)gridDim.x * blockDim.x * 4;
    for (long i = ((long)blockIdx.x * blockDim.x + threadIdx.x) * 4; i < n; i += stride) {
        float4 v = *(const float4*)(w + i);
        char4 q;
        q.x = (signed char)fminf(1.f, fmaxf(-1.f, rintf(v.x * sw)));
        q.y = (signed char)fminf(1.f, fmaxf(-1.f, rintf(v.y * sw)));
        q.z = (signed char)fminf(1.f, fmaxf(-1.f, rintf(v.z * sw)));
        q.w = (signed char)fminf(1.f, fmaxf(-1.f, rintf(v.w * sw)));
        *(char4*)(wq + i) = q;
    }
}

__global__ void quant_act(const float* __restrict__ x, signed char* __restrict__ xq,
                          float* __restrict__ ainv, int ncols) {
    __shared__ float red[256];
    int tid = threadIdx.x;
    long base = (long)blockIdx.x * ncols;
    float mx = 0.f;
    for (int i = tid; i < ncols; i += 256) mx = fmaxf(mx, fabsf(x[base + i]));
    red[tid] = mx;
    __syncthreads();
    for (int o = 128; o > 0; o >>= 1) {
        if (tid < o) red[tid] = fmaxf(red[tid], red[tid + o]);
        __syncthreads();
    }
    float cm = fmaxf(red[0], 1e-5f);
    float s = 127.f / cm;
    if (tid == 0) ainv[blockIdx.x] = cm * (1.f / 127.f);
    for (int i = tid; i < ncols; i += 256) {
        float v = rintf(x[base + i] * s);
        v = fminf(127.f, fmaxf(-128.f, v));
        xq[base + i] = (signed char)v;
    }
}

__global__ void rmsnorm_quant(const float* __restrict__ h, const float* __restrict__ lnw,
                              signed char* __restrict__ hq, float* __restrict__ hinv) {
    __shared__ float sh[Idim];
    __shared__ float red[256];
    int tid = threadIdx.x;
    long base = (long)blockIdx.x * Idim;
    float ss = 0.f;
    for (int i = tid; i < Idim; i += 256) {
        float v = h[base + i];
        sh[i] = v;
        ss += v * v;
    }
    red[tid] = ss;
    __syncthreads();
    for (int o = 128; o > 0; o >>= 1) {
        if (tid < o) red[tid] += red[tid + o];
        __syncthreads();
    }
    float rs = rsqrtf(red[0] / (float)Idim + 1e-6f);
    __syncthreads();
    float mx = 0.f;
    for (int i = tid; i < Idim; i += 256) {
        float hn = lnw[i] * sh[i] * rs;
        sh[i] = hn;
        mx = fmaxf(mx, fabsf(hn));
    }
    red[tid] = mx;
    __syncthreads();
    for (int o = 128; o > 0; o >>= 1) {
        if (tid < o) red[tid] = fmaxf(red[tid], red[tid + o]);
        __syncthreads();
    }
    float cm = fmaxf(red[0], 1e-5f);
    float s = 127.f / cm;
    if (tid == 0) hinv[blockIdx.x] = cm * (1.f / 127.f);
    for (int i = tid; i < Idim; i += 256) {
        float v = rintf(sh[i] * s);
        v = fminf(127.f, fmaxf(-128.f, v));
        hq[base + i] = (signed char)v;
    }
}

// ======================= IMMA GEMM =======================
// C[m,n] = rowinv[m]*winv * sum_k A[m,k]*B[n,k], A/B int8 k-contiguous.
// CTA tile 128x128, K-chunk 128 bytes. 512 threads = 16 warps (4x4), warp tile 32x32.
// NB=2: B0=gate, B1=up; epilogue writes silu(g)*u.  NB=1: plain scaled output.
template<int NB, int STAGES>
__global__ void __launch_bounds__(512, 1)
gemm_mma(const signed char* __restrict__ A,
         const signed char* __restrict__ B0,
         const signed char* __restrict__ B1,
         float* __restrict__ C,
         int Kb, int NC, int Nout,
         const float* __restrict__ rowinv, int iw0, int iw1)
{
    extern __shared__ char smem[];
    const uint32_t db = (smem_u32(smem) + 1023u) & 0xFFFFFC00u;
    const int tid = threadIdx.x;
    const int lane = tid & 31;
    const int wid = tid >> 5;
    const int wm = wid >> 2, wn = wid & 3;
    const int m0 = blockIdx.x * 128, n0 = blockIdx.y * 128;
    constexpr int NBUF = NB + 1;
    constexpr uint32_t STAGE_B = NBUF * 16384u;

    const signed char* srcA = A + (size_t)m0 * Kb;
    const signed char* srcB0 = B0 + (size_t)n0 * Kb;
    const signed char* srcB1 = B1 + (size_t)n0 * Kb;

    int acc[NB][2][4][4];
#pragma unroll
    for (int b = 0; b < NB; b++)
#pragma unroll
        for (int mt = 0; mt < 2; mt++)
#pragma unroll
            for (int n8 = 0; n8 < 4; n8++)
#pragma unroll
                for (int q = 0; q < 4; q++) acc[b][mt][n8][q] = 0;

    // ---- ldmatrix lane address components (constant across chunks) ----
    const int arow = (lane & 7) + ((lane & 8) ? 8 : 0);   // + mt*16 + wm*32
    const int acol = (lane >> 4);                          // + s*2
    const int brow = (lane & 7) + ((lane & 16) ? 8 : 0);  // + nt*16 + wn*32
    const int bcol = ((lane >> 3) & 1);                    // + s*2

    auto load_stage = [&](int chunk) {
        uint32_t base = db + (uint32_t)(chunk % STAGES) * STAGE_B;
        size_t coff = (size_t)chunk * 128;
#pragma unroll
        for (int it = 0; it < 2; it++) {
            int idx = tid + it * 512;
            int row = idx >> 3, c16 = idx & 7;
            uint32_t sw = row * 128 + ((c16 ^ (row & 7)) << 4);
            size_t go = (size_t)row * Kb + coff + c16 * 16;
            cp16(base + sw, srcA + go);
            cp16(base + 16384 + sw, srcB0 + go);
            if (NB == 2) cp16(base + 32768 + sw, srcB1 + go);
        }
    };

    int fill = 0;
    for (; fill < STAGES - 1; fill++) { load_stage(fill); CP_COMMIT(); }

    for (int j = 0; j < NC; j++) {
        if (fill < NC) load_stage(fill);
        CP_COMMIT();
        fill++;
        cp_wait<STAGES - 1>();
        __syncthreads();

        uint32_t abase = db + (uint32_t)(j % STAGES) * STAGE_B;
#pragma unroll
        for (int s = 0; s < 4; s++) {
            uint32_t af[2][4];
#pragma unroll
            for (int mt = 0; mt < 2; mt++) {
                int row = wm * 32 + mt * 16 + arow;
                int c16 = s * 2 + acol;
                uint32_t addr = abase + row * 128 + ((c16 ^ (row & 7)) << 4);
                LDSM4(af[mt], addr);
            }
#pragma unroll
            for (int b = 0; b < NB; b++) {
                uint32_t bb = abase + 16384u + (uint32_t)b * 16384u;
#pragma unroll
                for (int nt = 0; nt < 2; nt++) {
                    uint32_t bf[4];
                    int row = wn * 32 + nt * 16 + brow;
                    int c16 = s * 2 + bcol;
                    uint32_t addr = bb + row * 128 + ((c16 ^ (row & 7)) << 4);
                    LDSM4(bf, addr);
#pragma unroll
                    for (int mt = 0; mt < 2; mt++) {
                        MMA_S8(acc[b][mt][nt * 2 + 0], af[mt], bf[0], bf[1]);
                        MMA_S8(acc[b][mt][nt * 2 + 1], af[mt], bf[2], bf[3]);
                    }
                }
            }
        }
        __syncthreads();
    }

    // ---- epilogue ----
#pragma unroll
    for (int mt = 0; mt < 2; mt++) {
        int r = m0 + wm * 32 + mt * 16 + (lane >> 2);   // rows r, r+8
        float ai0 = rowinv[r], ai1 = rowinv[r + 8];
        float* crow0 = C + (size_t)r * Nout;
        float* crow1 = C + (size_t)(r + 8) * Nout;
        if (NB == 2) {
            float wg0 = g_winv[iw0], wu0 = g_winv[iw1];
            float sg0 = ai0 * wg0, su0 = ai0 * wu0;
            float sg1 = ai1 * wg0, su1 = ai1 * wu0;
#pragma unroll
            for (int n8 = 0; n8 < 4; n8++) {
                int c = n0 + wn * 32 + n8 * 8 + (lane & 3) * 2;
                float g00 = (float)acc[0][mt][n8][0] * sg0;
                float g01 = (float)acc[0][mt][n8][1] * sg0;
                float g10 = (float)acc[0][mt][n8][2] * sg1;
                float g11 = (float)acc[0][mt][n8][3] * sg1;
                float u00 = (float)acc[1][mt][n8][0] * su0;
                float u01 = (float)acc[1][mt][n8][1] * su0;
                float u10 = (float)acc[1][mt][n8][2] * su1;
                float u11 = (float)acc[1][mt][n8][3] * su1;
                float2 o0, o1;
                o0.x = (g00 / (1.f + expf(-g00))) * u00;
                o0.y = (g01 / (1.f + expf(-g01))) * u01;
                o1.x = (g10 / (1.f + expf(-g10))) * u10;
                o1.y = (g11 / (1.f + expf(-g11))) * u11;
                *(float2*)(crow0 + c) = o0;
                *(float2*)(crow1 + c) = o1;
            }
        } else {
            float w0 = g_winv[iw0];
            float s0 = ai0 * w0, s1 = ai1 * w0;
#pragma unroll
            for (int n8 = 0; n8 < 4; n8++) {
                int c = n0 + wn * 32 + n8 * 8 + (lane & 3) * 2;
                float2 o0, o1;
                o0.x = (float)acc[0][mt][n8][0] * s0;
                o0.y = (float)acc[0][mt][n8][1] * s0;
                o1.x = (float)acc[0][mt][n8][2] * s1;
                o1.y = (float)acc[0][mt][n8][3] * s1;
                *(float2*)(crow0 + c) = o0;
                *(float2*)(crow1 + c) = o1;
            }
        }
    }
}

// ======================= launch =======================
extern "C" void kernel_launch(void* const* d_in, const int* in_sizes, int n_in,
                              void* d_out, int out_size) {
    const float* x   = (const float*)d_in[0];
    const float* wg  = (const float*)d_in[1];
    const float* wu  = (const float*)d_in[2];
    const float* wd  = (const float*)d_in[3];
    const float* lnw = (const float*)d_in[4];
    float* out = (float*)d_out;

    signed char *wqg, *wqu, *wqd, *xq, *hq;
    float *gbuf, *ainv, *hinv;
    cudaGetSymbolAddress((void**)&wqg, g_wqg);
    cudaGetSymbolAddress((void**)&wqu, g_wqu);
    cudaGetSymbolAddress((void**)&wqd, g_wqd);
    cudaGetSymbolAddress((void**)&xq, g_xq);
    cudaGetSymbolAddress((void**)&hq, g_hq);
    cudaGetSymbolAddress((void**)&gbuf, g_gbuf);
    cudaGetSymbolAddress((void**)&ainv, g_ainv);
    cudaGetSymbolAddress((void**)&hinv, g_hinv);

    const int SMEM2 = 3 * 3 * 16384 + 1024;   // 148480
    const int SMEM1 = 4 * 2 * 16384 + 1024;   // 132096
    cudaFuncSetAttribute(gemm_mma<2, 3>, cudaFuncAttributeMaxDynamicSharedMemorySize, SMEM2);
    cudaFuncSetAttribute(gemm_mma<1, 4>, cudaFuncAttributeMaxDynamicSharedMemorySize, SMEM1);

    const long NWl = (long)NW;

    absmean_partial<<<2048, 256>>>(wg, NWl, 0);
    absmean_partial<<<2048, 256>>>(wu, NWl, 1);
    absmean_partial<<<2048, 256>>>(wd, NWl, 2);
    finalize_scales<<<3, 256>>>(NWl);

    quant_weight<<<4096, 256>>>(wg, wqg, NWl, 0);
    quant_weight<<<4096, 256>>>(wu, wqu, NWl, 1);
    quant_weight<<<4096, 256>>>(wd, wqd, NWl, 2);

    quant_act<<<Tdim, 256>>>(x, xq, ainv, Hdim);

    // fused gate+up GEMM -> h = silu(g)*u  [T, I]
    gemm_mma<2, 3><<<dim3(Tdim / 128, Idim / 128), 512, SMEM2>>>(
        xq, wqg, wqu, gbuf, Hdim, Hdim / 128, Idim, ainv, 0, 1);

    rmsnorm_quant<<<Tdim, 256>>>(gbuf, lnw, hq, hinv);

    // down GEMM -> out [T, H]
    gemm_mma<1, 4><<<dim3(Tdim / 128, Hdim / 128), 512, SMEM1>>>(
        hq, wqd, wqd, out, Idim, Idim / 128, Hdim, hinv, 2, 2);
}

// round 5
// speedup vs baseline: 1.1467x; 1.0037x over previous
#include <cuda_runtime.h>
#include <math.h>
#include <stdint.h>

#define Tdim 4096
#define Hdim 4096
#define Idim 11008
#define NW ((size_t)Idim*(size_t)Hdim)

// ---- static device scratch (no cudaMalloc allowed) ----
__device__ __align__(16) signed char g_wqg[NW];
__device__ __align__(16) signed char g_wqu[NW];
__device__ __align__(16) signed char g_wqd[NW];
__device__ __align__(16) signed char g_xq[(size_t)Tdim*Hdim];
__device__ __align__(16) signed char g_hq[(size_t)Tdim*Idim];
__device__ float g_gbuf[(size_t)Tdim*Idim];
__device__ float g_ainv[Tdim];
__device__ float g_hinv[Tdim];
__device__ float g_partial[3][2048];
__device__ float g_wscale[3];
__device__ float g_winv[3];
__device__ unsigned g_cnt = 0;

// ======================= PTX helpers =======================
__device__ __forceinline__ uint32_t smem_u32(const void* p) {
    uint32_t a;
    asm("{ .reg .u64 t; cvta.to.shared.u64 t, %1; cvt.u32.u64 %0, t; }" : "=r"(a) : "l"(p));
    return a;
}
__device__ __forceinline__ void cp16(uint32_t dst, const void* src) {
    asm volatile("cp.async.cg.shared.global [%0], [%1], 16;" :: "r"(dst), "l"(src));
}
#define CP_COMMIT() asm volatile("cp.async.commit_group;" ::: "memory")
template<int N> __device__ __forceinline__ void cp_wait() {
    asm volatile("cp.async.wait_group %0;" :: "n"(N) : "memory");
}
#define LDSM4(r, a) asm volatile( \
    "ldmatrix.sync.aligned.m8n8.x4.shared.b16 {%0,%1,%2,%3}, [%4];" \
    : "=r"((r)[0]), "=r"((r)[1]), "=r"((r)[2]), "=r"((r)[3]) : "r"(a))
#define MMA_S8(d, a, b0, b1) asm volatile( \
    "mma.sync.aligned.m16n8k32.row.col.s32.s8.s8.s32 " \
    "{%0,%1,%2,%3}, {%4,%5,%6,%7}, {%8,%9}, {%0,%1,%2,%3};" \
    : "+r"((d)[0]), "+r"((d)[1]), "+r"((d)[2]), "+r"((d)[3]) \
    : "r"((a)[0]), "r"((a)[1]), "r"((a)[2]), "r"((a)[3]), "r"(b0), "r"(b1))

// ======================= fused absmean + finalize =======================
__global__ void absmean_all(const float* __restrict__ wg, const float* __restrict__ wu,
                            const float* __restrict__ wd, long n) {
    __shared__ float red[256];
    __shared__ double redd[256];
    __shared__ bool amLast;
    int which = blockIdx.y;
    const float* w = which == 0 ? wg : (which == 1 ? wu : wd);
    float s = 0.f;
    long stride = (long)gridDim.x * blockDim.x;
    for (long i = (long)blockIdx.x * blockDim.x + threadIdx.x; i < n; i += stride)
        s += fabsf(w[i]);
    red[threadIdx.x] = s;
    __syncthreads();
    for (int o = 128; o > 0; o >>= 1) {
        if (threadIdx.x < o) red[threadIdx.x] += red[threadIdx.x + o];
        __syncthreads();
    }
    if (threadIdx.x == 0) {
        g_partial[which][blockIdx.x] = red[0];
        __threadfence();
        unsigned t = atomicAdd(&g_cnt, 1u);
        amLast = (t == gridDim.x * 3 - 1);
    }
    __syncthreads();
    if (amLast) {
        for (int m = 0; m < 3; m++) {
            double s2 = 0.0;
            for (int i = threadIdx.x; i < 2048; i += 256) s2 += (double)g_partial[m][i];
            redd[threadIdx.x] = s2;
            __syncthreads();
            for (int o = 128; o > 0; o >>= 1) {
                if (threadIdx.x < o) redd[threadIdx.x] += redd[threadIdx.x + o];
                __syncthreads();
            }
            if (threadIdx.x == 0) {
                float mean = (float)(redd[0] / (double)n);
                float cm = fmaxf(mean, 1e-5f);
                g_wscale[m] = 1.f / cm;
                g_winv[m] = cm;
            }
            __syncthreads();
        }
        if (threadIdx.x == 0) g_cnt = 0;   // reset for next graph replay
    }
}

// ======================= weight quant (all 3 in one launch) =======================
__global__ void quant_weight_all(const float* __restrict__ wg, const float* __restrict__ wu,
                                 const float* __restrict__ wd, long n) {
    int which = blockIdx.y;
    const float* w = which == 0 ? wg : (which == 1 ? wu : wd);
    signed char* wq = which == 0 ? g_wqg : (which == 1 ? g_wqu : g_wqd);
    float sw = g_wscale[which];
    long stride = (long)gridDim.x * blockDim.x * 4;
    for (long i = ((long)blockIdx.x * blockDim.x + threadIdx.x) * 4; i < n; i += stride) {
        float4 v = *(const float4*)(w + i);
        char4 q;
        q.x = (signed char)fminf(1.f, fmaxf(-1.f, rintf(v.x * sw)));
        q.y = (signed char)fminf(1.f, fmaxf(-1.f, rintf(v.y * sw)));
        q.z = (signed char)fminf(1.f, fmaxf(-1.f, rintf(v.z * sw)));
        q.w = (signed char)fminf(1.f, fmaxf(-1.f, rintf(v.w * sw)));
        *(char4*)(wq + i) = q;
    }
}

__global__ void quant_act(const float* __restrict__ x, signed char* __restrict__ xq,
                          float* __restrict__ ainv, int ncols) {
    __shared__ float red[256];
    int tid = threadIdx.x;
    long base = (long)blockIdx.x * ncols;
    float mx = 0.f;
    for (int i = tid; i < ncols; i += 256) mx = fmaxf(mx, fabsf(x[base + i]));
    red[tid] = mx;
    __syncthreads();
    for (int o = 128; o > 0; o >>= 1) {
        if (tid < o) red[tid] = fmaxf(red[tid], red[tid + o]);
        __syncthreads();
    }
    float cm = fmaxf(red[0], 1e-5f);
    float s = 127.f / cm;
    if (tid == 0) ainv[blockIdx.x] = cm * (1.f / 127.f);
    for (int i = tid; i < ncols; i += 256) {
        float v = rintf(x[base + i] * s);
        v = fminf(127.f, fmaxf(-128.f, v));
        xq[base + i] = (signed char)v;
    }
}

__global__ void rmsnorm_quant(const float* __restrict__ h, const float* __restrict__ lnw,
                              signed char* __restrict__ hq, float* __restrict__ hinv) {
    __shared__ float sh[Idim];
    __shared__ float red[256];
    int tid = threadIdx.x;
    long base = (long)blockIdx.x * Idim;
    float ss = 0.f;
    for (int i = tid; i < Idim; i += 256) {
        float v = h[base + i];
        sh[i] = v;
        ss += v * v;
    }
    red[tid] = ss;
    __syncthreads();
    for (int o = 128; o > 0; o >>= 1) {
        if (tid < o) red[tid] += red[tid + o];
        __syncthreads();
    }
    float rs = rsqrtf(red[0] / (float)Idim + 1e-6f);
    __syncthreads();
    float mx = 0.f;
    for (int i = tid; i < Idim; i += 256) {
        float hn = lnw[i] * sh[i] * rs;
        sh[i] = hn;
        mx = fmaxf(mx, fabsf(hn));
    }
    red[tid] = mx;
    __syncthreads();
    for (int o = 128; o > 0; o >>= 1) {
        if (tid < o) red[tid] = fmaxf(red[tid], red[tid + o]);
        __syncthreads();
    }
    float cm = fmaxf(red[0], 1e-5f);
    float s = 127.f / cm;
    if (tid == 0) hinv[blockIdx.x] = cm * (1.f / 127.f);
    for (int i = tid; i < Idim; i += 256) {
        float v = rintf(sh[i] * s);
        v = fminf(127.f, fmaxf(-128.f, v));
        hq[base + i] = (signed char)v;
    }
}

// ======================= IMMA GEMM, 256-byte K-chunks =======================
// C[m,n] = rowinv[m]*winv * sum_k A[m,k]*B[n,k], A/B int8 K-contiguous.
// CTA 128x128, 512 threads = 16 warps (4x4), warp tile 32x32 (per B matrix).
// K-chunk = 256 bytes -> 8 MMA s-steps per chunk, 2 barriers per chunk.
template<int NB, int STAGES>
__global__ void __launch_bounds__(512, 1)
gemm_mma(const signed char* __restrict__ A,
         const signed char* __restrict__ B0,
         const signed char* __restrict__ B1,
         float* __restrict__ C,
         int Kb, int NC, int Nout,
         const float* __restrict__ rowinv, int iw0, int iw1)
{
    extern __shared__ char smem[];
    const uint32_t db = (smem_u32(smem) + 1023u) & 0xFFFFFC00u;
    const int tid = threadIdx.x;
    const int lane = tid & 31;
    const int wid = tid >> 5;
    const int wm = wid >> 2, wn = wid & 3;
    const int m0 = blockIdx.x * 128, n0 = blockIdx.y * 128;
    constexpr uint32_t MAT_B = 32768u;              // 128 rows x 256 B
    constexpr uint32_t STAGE_B = (NB + 1) * MAT_B;

    const signed char* srcA = A + (size_t)m0 * Kb;
    const signed char* srcB0 = B0 + (size_t)n0 * Kb;
    const signed char* srcB1 = B1 + (size_t)n0 * Kb;

    int acc[NB][2][4][4];
#pragma unroll
    for (int b = 0; b < NB; b++)
#pragma unroll
        for (int mt = 0; mt < 2; mt++)
#pragma unroll
            for (int n8 = 0; n8 < 4; n8++)
#pragma unroll
                for (int q = 0; q < 4; q++) acc[b][mt][n8][q] = 0;

    const int arow = (lane & 7) + ((lane & 8) ? 8 : 0);
    const int acol = (lane >> 4);
    const int brow = (lane & 7) + ((lane & 16) ? 8 : 0);
    const int bcol = ((lane >> 3) & 1);

    auto swz = [](int row, int c16) -> uint32_t {
        return (uint32_t)(row * 256 + ((((c16 & 7) ^ (row & 7)) | (c16 & 8)) << 4));
    };

    auto load_stage = [&](int chunk) {
        uint32_t base = db + (uint32_t)(chunk % STAGES) * STAGE_B;
        size_t coff = (size_t)chunk * 256;
#pragma unroll
        for (int it = 0; it < 4; it++) {
            int idx = tid + it * 512;          // 0..2047
            int row = idx >> 4, c16 = idx & 15;
            uint32_t sw = swz(row, c16);
            size_t go = (size_t)row * Kb + coff + c16 * 16;
            cp16(base + sw, srcA + go);
            cp16(base + MAT_B + sw, srcB0 + go);
            if (NB == 2) cp16(base + 2 * MAT_B + sw, srcB1 + go);
        }
    };

    int fill = 0;
    for (; fill < STAGES - 1; fill++) { load_stage(fill); CP_COMMIT(); }

    for (int j = 0; j < NC; j++) {
        if (fill < NC) load_stage(fill);
        CP_COMMIT();
        fill++;
        cp_wait<STAGES - 1>();
        __syncthreads();

        uint32_t abase = db + (uint32_t)(j % STAGES) * STAGE_B;
#pragma unroll
        for (int s = 0; s < 8; s++) {
            uint32_t af[2][4];
#pragma unroll
            for (int mt = 0; mt < 2; mt++) {
                int row = wm * 32 + mt * 16 + arow;
                LDSM4(af[mt], abase + swz(row, s * 2 + acol));
            }
#pragma unroll
            for (int b = 0; b < NB; b++) {
                uint32_t bb = abase + MAT_B + (uint32_t)b * MAT_B;
#pragma unroll
                for (int nt = 0; nt < 2; nt++) {
                    uint32_t bf[4];
                    int row = wn * 32 + nt * 16 + brow;
                    LDSM4(bf, bb + swz(row, s * 2 + bcol));
#pragma unroll
                    for (int mt = 0; mt < 2; mt++) {
                        MMA_S8(acc[b][mt][nt * 2 + 0], af[mt], bf[0], bf[1]);
                        MMA_S8(acc[b][mt][nt * 2 + 1], af[mt], bf[2], bf[3]);
                    }
                }
            }
        }
        __syncthreads();
    }

    // ---- epilogue ----
#pragma unroll
    for (int mt = 0; mt < 2; mt++) {
        int r = m0 + wm * 32 + mt * 16 + (lane >> 2);
        float ai0 = rowinv[r], ai1 = rowinv[r + 8];
        float* crow0 = C + (size_t)r * Nout;
        float* crow1 = C + (size_t)(r + 8) * Nout;
        if (NB == 2) {
            float wg0 = g_winv[iw0], wu0 = g_winv[iw1];
            float sg0 = ai0 * wg0, su0 = ai0 * wu0;
            float sg1 = ai1 * wg0, su1 = ai1 * wu0;
#pragma unroll
            for (int n8 = 0; n8 < 4; n8++) {
                int c = n0 + wn * 32 + n8 * 8 + (lane & 3) * 2;
                float g00 = (float)acc[0][mt][n8][0] * sg0;
                float g01 = (float)acc[0][mt][n8][1] * sg0;
                float g10 = (float)acc[0][mt][n8][2] * sg1;
                float g11 = (float)acc[0][mt][n8][3] * sg1;
                float u00 = (float)acc[1][mt][n8][0] * su0;
                float u01 = (float)acc[1][mt][n8][1] * su0;
                float u10 = (float)acc[1][mt][n8][2] * su1;
                float u11 = (float)acc[1][mt][n8][3] * su1;
                float2 o0, o1;
                o0.x = (g00 / (1.f + expf(-g00))) * u00;
                o0.y = (g01 / (1.f + expf(-g01))) * u01;
                o1.x = (g10 / (1.f + expf(-g10))) * u10;
                o1.y = (g11 / (1.f + expf(-g11))) * u11;
                *(float2*)(crow0 + c) = o0;
                *(float2*)(crow1 + c) = o1;
            }
        } else {
            float w0 = g_winv[iw0];
            float s0 = ai0 * w0, s1 = ai1 * w0;
#pragma unroll
            for (int n8 = 0; n8 < 4; n8++) {
                int c = n0 + wn * 32 + n8 * 8 + (lane & 3) * 2;
                float2 o0, o1;
                o0.x = (float)acc[0][mt][n8][0] * s0;
                o0.y = (float)acc[0][mt][n8][1] * s0;
                o1.x = (float)acc[0][mt][n8][2] * s1;
                o1.y = (float)acc[0][mt][n8][3] * s1;
                *(float2*)(crow0 + c) = o0;
                *(float2*)(crow1 + c) = o1;
            }
        }
    }
}

// ======================= launch =======================
extern "C" void kernel_launch(void* const* d_in, const int* in_sizes, int n_in,
                              void* d_out, int out_size) {
    const float* x   = (const float*)d_in[0];
    const float* wg  = (const float*)d_in[1];
    const float* wu  = (const float*)d_in[2];
    const float* wd  = (const float*)d_in[3];
    const float* lnw = (const float*)d_in[4];
    float* out = (float*)d_out;

    signed char *wqg, *wqu, *wqd, *xq, *hq;
    float *gbuf, *ainv, *hinv;
    cudaGetSymbolAddress((void**)&wqg, g_wqg);
    cudaGetSymbolAddress((void**)&wqu, g_wqu);
    cudaGetSymbolAddress((void**)&wqd, g_wqd);
    cudaGetSymbolAddress((void**)&xq, g_xq);
    cudaGetSymbolAddress((void**)&hq, g_hq);
    cudaGetSymbolAddress((void**)&gbuf, g_gbuf);
    cudaGetSymbolAddress((void**)&ainv, g_ainv);
    cudaGetSymbolAddress((void**)&hinv, g_hinv);

    const int SMEM2 = 2 * 3 * 32768 + 1024;   // 197632
    const int SMEM1 = 3 * 2 * 32768 + 1024;   // 197632
    cudaFuncSetAttribute(gemm_mma<2, 2>, cudaFuncAttributeMaxDynamicSharedMemorySize, SMEM2);
    cudaFuncSetAttribute(gemm_mma<1, 3>, cudaFuncAttributeMaxDynamicSharedMemorySize, SMEM1);

    const long NWl = (long)NW;

    // launch 0: absmean + fused finalize
    absmean_all<<<dim3(2048, 3), 256>>>(wg, wu, wd, NWl);
    // launch 1: all three weight quantizations
    quant_weight_all<<<dim3(2048, 3), 256>>>(wg, wu, wd, NWl);
    // launch 2: activation quant
    quant_act<<<Tdim, 256>>>(x, xq, ainv, Hdim);
    // launch 3 (ncu-profiled slot): fused gate+up GEMM -> h = silu(g)*u  [T, I]
    gemm_mma<2, 2><<<dim3(Tdim / 128, Idim / 128), 512, SMEM2>>>(
        xq, wqg, wqu, gbuf, Hdim, Hdim / 256, Idim, ainv, 0, 1);
    // launch 4: rmsnorm + act quant
    rmsnorm_quant<<<Tdim, 256>>>(gbuf, lnw, hq, hinv);
    // launch 5: down GEMM -> out [T, H]
    gemm_mma<1, 3><<<dim3(Tdim / 128, Hdim / 128), 512, SMEM1>>>(
        hq, wqd, wqd, out, Idim, Idim / 256, Hdim, hinv, 2, 2);
}

// round 6
// speedup vs baseline: 1.5835x; 1.3809x over previous
#include <cuda_runtime.h>
#include <math.h>
#include <stdint.h>

#define Tdim 4096
#define Hdim 4096
#define Idim 11008
#define KH4 (Hdim/4)
#define KI4 (Idim/4)
#define NW ((size_t)Idim*(size_t)Hdim)

// ---- static device scratch ----
__device__ __align__(16) signed char g_wqg[NW];
__device__ __align__(16) signed char g_wqu[NW];
__device__ __align__(16) signed char g_wqd[NW];
__device__ __align__(16) int g_wqg_t[(size_t)KH4*Idim];
__device__ __align__(16) int g_wqu_t[(size_t)KH4*Idim];
__device__ __align__(16) int g_wqd_t[(size_t)KI4*Hdim];
__device__ __align__(16) signed char g_xq[(size_t)Tdim*Hdim];
__device__ __align__(16) int g_xq_t[(size_t)KH4*Tdim];
__device__ __align__(16) signed char g_hq[(size_t)Tdim*Idim];
__device__ __align__(16) int g_hq_t[(size_t)KI4*Tdim];
__device__ float g_gbuf[(size_t)Tdim*Idim];
__device__ float g_ainv[Tdim];
__device__ float g_hinv[Tdim];
__device__ float g_partial[3][2048];
__device__ float g_wscale[3];
__device__ float g_winv[3];
__device__ unsigned g_cnt = 0;

// ======================= PTX helpers =======================
__device__ __forceinline__ uint32_t smem_u32(const void* p) {
    uint32_t a;
    asm("{ .reg .u64 t; cvta.to.shared.u64 t, %1; cvt.u32.u64 %0, t; }" : "=r"(a) : "l"(p));
    return a;
}
__device__ __forceinline__ void cp16(uint32_t dst, const void* src) {
    asm volatile("cp.async.cg.shared.global [%0], [%1], 16;" :: "r"(dst), "l"(src));
}
#define CP_COMMIT() asm volatile("cp.async.commit_group;" ::: "memory")
template<int N> __device__ __forceinline__ void cp_wait() {
    asm volatile("cp.async.wait_group %0;" :: "n"(N) : "memory");
}
#define LDSM4(r, a) asm volatile( \
    "ldmatrix.sync.aligned.m8n8.x4.shared.b16 {%0,%1,%2,%3}, [%4];" \
    : "=r"((r)[0]), "=r"((r)[1]), "=r"((r)[2]), "=r"((r)[3]) : "r"(a))
#define MMA_S8(d, a, b0, b1) asm volatile( \
    "mma.sync.aligned.m16n8k32.row.col.s32.s8.s8.s32 " \
    "{%0,%1,%2,%3}, {%4,%5,%6,%7}, {%8,%9}, {%0,%1,%2,%3};" \
    : "+r"((d)[0]), "+r"((d)[1]), "+r"((d)[2]), "+r"((d)[3]) \
    : "r"((a)[0]), "r"((a)[1]), "r"((a)[2]), "r"((a)[3]), "r"(b0), "r"(b1))

// ======================= absmean + finalize =======================
__global__ void absmean_all(const float* __restrict__ wg, const float* __restrict__ wu,
                            const float* __restrict__ wd, long n) {
    __shared__ float red[256];
    __shared__ double redd[256];
    __shared__ bool amLast;
    int which = blockIdx.y;
    const float* w = which == 0 ? wg : (which == 1 ? wu : wd);
    float s = 0.f;
    long stride = (long)gridDim.x * blockDim.x;
    for (long i = (long)blockIdx.x * blockDim.x + threadIdx.x; i < n; i += stride)
        s += fabsf(w[i]);
    red[threadIdx.x] = s;
    __syncthreads();
    for (int o = 128; o > 0; o >>= 1) {
        if (threadIdx.x < o) red[threadIdx.x] += red[threadIdx.x + o];
        __syncthreads();
    }
    if (threadIdx.x == 0) {
        g_partial[which][blockIdx.x] = red[0];
        __threadfence();
        unsigned t = atomicAdd(&g_cnt, 1u);
        amLast = (t == gridDim.x * 3 - 1);
    }
    __syncthreads();
    if (amLast) {
        for (int m = 0; m < 3; m++) {
            double s2 = 0.0;
            for (int i = threadIdx.x; i < 2048; i += 256) s2 += (double)g_partial[m][i];
            redd[threadIdx.x] = s2;
            __syncthreads();
            for (int o = 128; o > 0; o >>= 1) {
                if (threadIdx.x < o) redd[threadIdx.x] += redd[threadIdx.x + o];
                __syncthreads();
            }
            if (threadIdx.x == 0) {
                float mean = (float)(redd[0] / (double)n);
                float cm = fmaxf(mean, 1e-5f);
                g_wscale[m] = 1.f / cm;
                g_winv[m] = cm;
            }
            __syncthreads();
        }
        if (threadIdx.x == 0) g_cnt = 0;
    }
}

// ======================= weight quant: emits row-major + word-transposed =======================
// tile: 128 n-rows x 128 f32 k-cols (= 32 k-words). block 256 threads.
__global__ void quant_weight_t(const float* __restrict__ w, int* __restrict__ wq32,
                               int* __restrict__ wqt32, int Kf, int N, int which) {
    __shared__ int s[32][132];
    float sw = g_wscale[which];
    int n0 = blockIdx.y * 128, kc0 = blockIdx.x * 128;
    int t = threadIdx.x;
    int r = t >> 1, h = t & 1;
    const float* wr = w + (size_t)(n0 + r) * Kf + kc0 + h * 64;
    int words[16];
#pragma unroll
    for (int q = 0; q < 16; q++) {
        float4 v = *(const float4*)(wr + q * 4);
        int b0 = (int)fminf(1.f, fmaxf(-1.f, rintf(v.x * sw)));
        int b1 = (int)fminf(1.f, fmaxf(-1.f, rintf(v.y * sw)));
        int b2 = (int)fminf(1.f, fmaxf(-1.f, rintf(v.z * sw)));
        int b3 = (int)fminf(1.f, fmaxf(-1.f, rintf(v.w * sw)));
        int word = (b0 & 0xFF) | ((b1 & 0xFF) << 8) | ((b2 & 0xFF) << 16) | (b3 << 24);
        words[q] = word;
        s[h * 16 + q][r] = word;
    }
    int Kw = Kf >> 2;
    int* dst = wq32 + (size_t)(n0 + r) * Kw + (kc0 >> 2) + h * 16;
#pragma unroll
    for (int q = 0; q < 16; q += 4)
        *(int4*)(dst + q) = make_int4(words[q], words[q+1], words[q+2], words[q+3]);
    __syncthreads();
    int kw = t >> 3, seg = t & 7;
    int* dstT = wqt32 + (size_t)((kc0 >> 2) + kw) * N + n0 + seg * 16;
#pragma unroll
    for (int q = 0; q < 16; q += 4) {
        int4 o = make_int4(s[kw][seg*16+q], s[kw][seg*16+q+1], s[kw][seg*16+q+2], s[kw][seg*16+q+3]);
        *(int4*)(dstT + q) = o;
    }
}

// ======================= int32 tiled transpose: dst[C][R] = src[R][C] =======================
__global__ void transpose32(const int* __restrict__ src, int* __restrict__ dst, int R, int C) {
    __shared__ int s[32][33];
    int x = blockIdx.x * 32 + threadIdx.x;
    int y0 = blockIdx.y * 32 + threadIdx.y;
#pragma unroll
    for (int j = 0; j < 32; j += 8)
        s[threadIdx.y + j][threadIdx.x] = src[(size_t)(y0 + j) * C + x];
    __syncthreads();
    int x2 = blockIdx.y * 32 + threadIdx.x;
#pragma unroll
    for (int j = 0; j < 32; j += 8)
        dst[(size_t)(blockIdx.x * 32 + threadIdx.y + j) * R + x2] = s[threadIdx.x][threadIdx.y + j];
}

// ======================= activation quant =======================
__global__ void quant_act(const float* __restrict__ x, signed char* __restrict__ xq,
                          float* __restrict__ ainv, int ncols) {
    __shared__ float red[256];
    int tid = threadIdx.x;
    long base = (long)blockIdx.x * ncols;
    float mx = 0.f;
    for (int i = tid; i < ncols; i += 256) mx = fmaxf(mx, fabsf(x[base + i]));
    red[tid] = mx;
    __syncthreads();
    for (int o = 128; o > 0; o >>= 1) {
        if (tid < o) red[tid] = fmaxf(red[tid], red[tid + o]);
        __syncthreads();
    }
    float cm = fmaxf(red[0], 1e-5f);
    float s = 127.f / cm;
    if (tid == 0) ainv[blockIdx.x] = cm * (1.f / 127.f);
    for (int i = tid; i < ncols; i += 256) {
        float v = rintf(x[base + i] * s);
        v = fminf(127.f, fmaxf(-128.f, v));
        xq[base + i] = (signed char)v;
    }
}

__global__ void rmsnorm_quant(const float* __restrict__ h, const float* __restrict__ lnw,
                              signed char* __restrict__ hq, float* __restrict__ hinv) {
    __shared__ float sh[Idim];
    __shared__ float red[256];
    int tid = threadIdx.x;
    long base = (long)blockIdx.x * Idim;
    float ss = 0.f;
    for (int i = tid; i < Idim; i += 256) {
        float v = h[base + i];
        sh[i] = v;
        ss += v * v;
    }
    red[tid] = ss;
    __syncthreads();
    for (int o = 128; o > 0; o >>= 1) {
        if (tid < o) red[tid] += red[tid + o];
        __syncthreads();
    }
    float rs = rsqrtf(red[0] / (float)Idim + 1e-6f);
    __syncthreads();
    float mx = 0.f;
    for (int i = tid; i < Idim; i += 256) {
        float hn = lnw[i] * sh[i] * rs;
        sh[i] = hn;
        mx = fmaxf(mx, fabsf(hn));
    }
    red[tid] = mx;
    __syncthreads();
    for (int o = 128; o > 0; o >>= 1) {
        if (tid < o) red[tid] = fmaxf(red[tid], red[tid + o]);
        __syncthreads();
    }
    float cm = fmaxf(red[0], 1e-5f);
    float s = 127.f / cm;
    if (tid == 0) hinv[blockIdx.x] = cm * (1.f / 127.f);
    for (int i = tid; i < Idim; i += 256) {
        float v = rintf(sh[i] * s);
        v = fminf(127.f, fmaxf(-128.f, v));
        hq[base + i] = (signed char)v;
    }
}

// ======================= hybrid MMA + dp4a GEMM =======================
// CTA tile 128M x 128N (per B matrix). warps 0-7: IMMA on cols [0,64); warps 8-15: dp4a cols [64,128).
// K-chunk = 128 bytes. A/B int8 K-major + word-transposed copies for the dp4a side.
template<int NB, int STAGES>
__global__ void __launch_bounds__(512, 1)
gemm_hyb(const signed char* __restrict__ A,     const signed char* __restrict__ At,
         const signed char* __restrict__ B0,    const signed char* __restrict__ B0t,
         const signed char* __restrict__ B1,    const signed char* __restrict__ B1t,
         float* __restrict__ C,
         int Kb, int NC, int Nout,
         const float* __restrict__ rowinv, int iw0, int iw1)
{
    extern __shared__ char smem[];
    char* sp = (char*)(((uintptr_t)smem + 1023u) & ~(uintptr_t)1023u);
    const uint32_t db = smem_u32(sp);
    const int tid = threadIdx.x;
    const int lane = tid & 31;
    const int wid = tid >> 5;
    const int m0 = blockIdx.x * 128, n0 = blockIdx.y * 128;

    constexpr uint32_t STAGE_B = (NB == 2) ? 65536u : 49152u;
    constexpr uint32_t AT_OFF  = (NB == 2) ? 32768u : 24576u;
    constexpr uint32_t B0T_OFF = (NB == 2) ? 49152u : 40960u;
    constexpr uint32_t B1T_OFF = 57344u;
    constexpr int NITER = (NB == 2) ? 8 : 6;
    constexpr int AT_BEG = (NB == 2) ? 2048 : 1536;
    constexpr int B0T_BEG = AT_BEG + 1024;

    const signed char* srcA  = A + (size_t)m0 * Kb;
    const signed char* srcB0 = B0 + (size_t)n0 * Kb;
    const signed char* srcB1 = B1 + (size_t)n0 * Kb;

    auto swz = [](int row, int c16) -> uint32_t {
        return (uint32_t)(row * 128 + ((c16 ^ (row & 7)) << 4));
    };

    auto load_stage = [&](int chunk) {
        uint32_t base = db + (uint32_t)(chunk % STAGES) * STAGE_B;
        int k0 = chunk * 128, kw0 = chunk * 32;
#pragma unroll
        for (int it = 0; it < NITER; it++) {
            int idx = tid + it * 512;
            if (idx < 1024) {
                int r = idx >> 3, c = idx & 7;
                cp16(base + swz(r, c), srcA + (size_t)r * Kb + k0 + c * 16);
            } else if (idx < 1536) {
                int j = idx - 1024, r = j >> 3, c = j & 7;
                cp16(base + 16384u + swz(r, c), srcB0 + (size_t)r * Kb + k0 + c * 16);
            } else if (NB == 2 && idx < 2048) {
                int j = idx - 1536, r = j >> 3, c = j & 7;
                cp16(base + 24576u + swz(r, c), srcB1 + (size_t)r * Kb + k0 + c * 16);
            } else if (idx < B0T_BEG) {
                int j = idx - AT_BEG, kk = j >> 5, w = j & 31;
                cp16(base + AT_OFF + kk * 512 + w * 16,
                     At + ((size_t)(kw0 + kk) * Tdim + m0) * 4 + w * 16);
            } else if (idx < B0T_BEG + 512) {
                int j = idx - B0T_BEG, kk = j >> 4, p = j & 15;
                cp16(base + B0T_OFF + kk * 256 + p * 16,
                     B0t + ((size_t)(kw0 + kk) * Nout + n0 + 64) * 4 + p * 16);
            } else {
                int j = idx - (B0T_BEG + 512), kk = j >> 4, p = j & 15;
                cp16(base + B1T_OFF + kk * 256 + p * 16,
                     B1t + ((size_t)(kw0 + kk) * Nout + n0 + 64) * 4 + p * 16);
            }
        }
    };

    // MMA-side state
    const int wm = wid >> 1, wn = wid & 1;
    const int arow = (lane & 7) + ((lane & 8) ? 8 : 0);
    const int acol = (lane >> 4);
    const int brow = (lane & 7) + ((lane & 16) ? 8 : 0);
    const int bcol = ((lane >> 3) & 1);
    int acc[NB][2][4][4];
#pragma unroll
    for (int b = 0; b < NB; b++)
#pragma unroll
        for (int mt = 0; mt < 2; mt++)
#pragma unroll
            for (int n8 = 0; n8 < 4; n8++)
#pragma unroll
                for (int q = 0; q < 4; q++) acc[b][mt][n8][q] = 0;

    // dp4a-side state
    const int dw = wid - 8;
    const int drow = (dw & 3) * 32 + ((lane >> 3) << 3);       // 8 rows
    const int dcol = ((dw >> 2) << 5) + ((lane & 7) << 2);     // 4 cols within [0,64)
    int dac0[8][4], dac1[8][4];
#pragma unroll
    for (int i = 0; i < 8; i++)
#pragma unroll
        for (int j = 0; j < 4; j++) { dac0[i][j] = 0; if (NB == 2) dac1[i][j] = 0; }

    int fill = 0;
    for (; fill < STAGES - 1; fill++) { load_stage(fill); CP_COMMIT(); }

    for (int ch = 0; ch < NC; ch++) {
        if (fill < NC) load_stage(fill);
        CP_COMMIT();
        fill++;
        cp_wait<STAGES - 1>();
        __syncthreads();

        uint32_t sboff = (uint32_t)(ch % STAGES) * STAGE_B;
        if (wid < 8) {
            uint32_t abase = db + sboff;
#pragma unroll
            for (int s = 0; s < 4; s++) {
                uint32_t af[2][4];
#pragma unroll
                for (int mt = 0; mt < 2; mt++) {
                    int row = wm * 32 + mt * 16 + arow;
                    LDSM4(af[mt], abase + swz(row, s * 2 + acol));
                }
#pragma unroll
                for (int b = 0; b < NB; b++) {
                    uint32_t bb = abase + 16384u + (uint32_t)b * 8192u;
#pragma unroll
                    for (int nt = 0; nt < 2; nt++) {
                        uint32_t bf[4];
                        int row = wn * 32 + nt * 16 + brow;
                        LDSM4(bf, bb + swz(row, s * 2 + bcol));
#pragma unroll
                        for (int mt = 0; mt < 2; mt++) {
                            MMA_S8(acc[b][mt][nt * 2 + 0], af[mt], bf[0], bf[1]);
                            MMA_S8(acc[b][mt][nt * 2 + 1], af[mt], bf[2], bf[3]);
                        }
                    }
                }
            }
        } else {
            const char* at  = sp + sboff + AT_OFF + drow * 4;
            const char* b0t = sp + sboff + B0T_OFF + dcol * 4;
            const char* b1t = sp + sboff + B1T_OFF + dcol * 4;
#pragma unroll 4
            for (int kk = 0; kk < 32; kk++) {
                int4 a0 = *(const int4*)(at + kk * 512);
                int4 a1 = *(const int4*)(at + kk * 512 + 16);
                int4 bv0 = *(const int4*)(b0t + kk * 256);
                int a[8] = {a0.x, a0.y, a0.z, a0.w, a1.x, a1.y, a1.z, a1.w};
                int b0w[4] = {bv0.x, bv0.y, bv0.z, bv0.w};
#pragma unroll
                for (int i = 0; i < 8; i++)
#pragma unroll
                    for (int j = 0; j < 4; j++)
                        dac0[i][j] = __dp4a(a[i], b0w[j], dac0[i][j]);
                if (NB == 2) {
                    int4 bv1 = *(const int4*)(b1t + kk * 256);
                    int b1w[4] = {bv1.x, bv1.y, bv1.z, bv1.w};
#pragma unroll
                    for (int i = 0; i < 8; i++)
#pragma unroll
                        for (int j = 0; j < 4; j++)
                            dac1[i][j] = __dp4a(a[i], b1w[j], dac1[i][j]);
                }
            }
        }
        __syncthreads();
    }

    // ======== epilogue ========
    float wg0 = g_winv[iw0], wu0 = (NB == 2) ? g_winv[iw1] : 0.f;
    if (wid < 8) {
#pragma unroll
        for (int mt = 0; mt < 2; mt++) {
            int r = m0 + wm * 32 + mt * 16 + (lane >> 2);
            float ai0 = rowinv[r], ai1 = rowinv[r + 8];
            float* crow0 = C + (size_t)r * Nout;
            float* crow1 = C + (size_t)(r + 8) * Nout;
            if (NB == 2) {
                float sg0 = ai0 * wg0, su0 = ai0 * wu0;
                float sg1 = ai1 * wg0, su1 = ai1 * wu0;
#pragma unroll
                for (int n8 = 0; n8 < 4; n8++) {
                    int c = n0 + wn * 32 + n8 * 8 + (lane & 3) * 2;
                    float g00 = (float)acc[0][mt][n8][0] * sg0;
                    float g01 = (float)acc[0][mt][n8][1] * sg0;
                    float g10 = (float)acc[0][mt][n8][2] * sg1;
                    float g11 = (float)acc[0][mt][n8][3] * sg1;
                    float u00 = (float)acc[1][mt][n8][0] * su0;
                    float u01 = (float)acc[1][mt][n8][1] * su0;
                    float u10 = (float)acc[1][mt][n8][2] * su1;
                    float u11 = (float)acc[1][mt][n8][3] * su1;
                    float2 o0, o1;
                    o0.x = (g00 / (1.f + expf(-g00))) * u00;
                    o0.y = (g01 / (1.f + expf(-g01))) * u01;
                    o1.x = (g10 / (1.f + expf(-g10))) * u10;
                    o1.y = (g11 / (1.f + expf(-g11))) * u11;
                    *(float2*)(crow0 + c) = o0;
                    *(float2*)(crow1 + c) = o1;
                }
            } else {
                float s0 = ai0 * wg0, s1 = ai1 * wg0;
#pragma unroll
                for (int n8 = 0; n8 < 4; n8++) {
                    int c = n0 + wn * 32 + n8 * 8 + (lane & 3) * 2;
                    float2 o0, o1;
                    o0.x = (float)acc[0][mt][n8][0] * s0;
                    o0.y = (float)acc[0][mt][n8][1] * s0;
                    o1.x = (float)acc[0][mt][n8][2] * s1;
                    o1.y = (float)acc[0][mt][n8][3] * s1;
                    *(float2*)(crow0 + c) = o0;
                    *(float2*)(crow1 + c) = o1;
                }
            }
        }
    } else {
        int cbase = n0 + 64 + dcol;
#pragma unroll
        for (int i = 0; i < 8; i++) {
            int r = m0 + drow + i;
            float ai = rowinv[r];
            float* crow = C + (size_t)r * Nout + cbase;
            if (NB == 2) {
                float sg = ai * wg0, su = ai * wu0;
                float4 o;
                float g0 = (float)dac0[i][0] * sg, u0 = (float)dac1[i][0] * su;
                float g1 = (float)dac0[i][1] * sg, u1 = (float)dac1[i][1] * su;
                float g2 = (float)dac0[i][2] * sg, u2 = (float)dac1[i][2] * su;
                float g3 = (float)dac0[i][3] * sg, u3 = (float)dac1[i][3] * su;
                o.x = (g0 / (1.f + expf(-g0))) * u0;
                o.y = (g1 / (1.f + expf(-g1))) * u1;
                o.z = (g2 / (1.f + expf(-g2))) * u2;
                o.w = (g3 / (1.f + expf(-g3))) * u3;
                *(float4*)crow = o;
            } else {
                float sc = ai * wg0;
                float4 o;
                o.x = (float)dac0[i][0] * sc;
                o.y = (float)dac0[i][1] * sc;
                o.z = (float)dac0[i][2] * sc;
                o.w = (float)dac0[i][3] * sc;
                *(float4*)crow = o;
            }
        }
    }
}

// ======================= launch =======================
extern "C" void kernel_launch(void* const* d_in, const int* in_sizes, int n_in,
                              void* d_out, int out_size) {
    const float* x   = (const float*)d_in[0];
    const float* wg  = (const float*)d_in[1];
    const float* wu  = (const float*)d_in[2];
    const float* wd  = (const float*)d_in[3];
    const float* lnw = (const float*)d_in[4];
    float* out = (float*)d_out;

    signed char *wqg, *wqu, *wqd, *xq, *hq;
    int *wqg_t, *wqu_t, *wqd_t, *xq_t, *hq_t;
    float *gbuf, *ainv, *hinv;
    cudaGetSymbolAddress((void**)&wqg, g_wqg);
    cudaGetSymbolAddress((void**)&wqu, g_wqu);
    cudaGetSymbolAddress((void**)&wqd, g_wqd);
    cudaGetSymbolAddress((void**)&wqg_t, g_wqg_t);
    cudaGetSymbolAddress((void**)&wqu_t, g_wqu_t);
    cudaGetSymbolAddress((void**)&wqd_t, g_wqd_t);
    cudaGetSymbolAddress((void**)&xq, g_xq);
    cudaGetSymbolAddress((void**)&xq_t, g_xq_t);
    cudaGetSymbolAddress((void**)&hq, g_hq);
    cudaGetSymbolAddress((void**)&hq_t, g_hq_t);
    cudaGetSymbolAddress((void**)&gbuf, g_gbuf);
    cudaGetSymbolAddress((void**)&ainv, g_ainv);
    cudaGetSymbolAddress((void**)&hinv, g_hinv);

    const int SMEM = 3 * 65536 + 1024;   // 197632 (both kernels: 3x64K / 4x48K = 192K + pad)
    cudaFuncSetAttribute(gemm_hyb<2, 3>, cudaFuncAttributeMaxDynamicSharedMemorySize, SMEM);
    cudaFuncSetAttribute(gemm_hyb<1, 4>, cudaFuncAttributeMaxDynamicSharedMemorySize, SMEM);

    const long NWl = (long)NW;

    // 0: scales
    absmean_all<<<dim3(2048, 3), 256>>>(wg, wu, wd, NWl);
    // 1: act quant
    quant_act<<<Tdim, 256>>>(x, xq, ainv, Hdim);
    // 2: xq word-transpose  [T][KH4] -> [KH4][T]
    transpose32<<<dim3(KH4 / 32, Tdim / 32), dim3(32, 8)>>>((const int*)xq, xq_t, Tdim, KH4);
    // 3-4: gate/up weight quant (+transposed)
    quant_weight_t<<<dim3(Hdim / 128, Idim / 128), 256>>>(wg, (int*)wqg, wqg_t, Hdim, Idim, 0);
    quant_weight_t<<<dim3(Hdim / 128, Idim / 128), 256>>>(wu, (int*)wqu, wqu_t, Hdim, Idim, 1);
    // 5: fused gate+up hybrid GEMM -> h = silu(g)*u  [T, I]
    gemm_hyb<2, 3><<<dim3(Tdim / 128, Idim / 128), 512, SMEM>>>(
        xq, (const signed char*)xq_t, wqg, (const signed char*)wqg_t,
        wqu, (const signed char*)wqu_t, gbuf, Hdim, Hdim / 128, Idim, ainv, 0, 1);
    // 6: rmsnorm + act quant
    rmsnorm_quant<<<Tdim, 256>>>(gbuf, lnw, hq, hinv);
    // 7: hq word-transpose  [T][KI4] -> [KI4][T]
    transpose32<<<dim3(KI4 / 32, Tdim / 32), dim3(32, 8)>>>((const int*)hq, hq_t, Tdim, KI4);
    // 8: down weight quant (+transposed)
    quant_weight_t<<<dim3(Idim / 128, Hdim / 128), 256>>>(wd, (int*)wqd, wqd_t, Idim, Hdim, 2);
    // 9: down hybrid GEMM -> out [T, H]
    gemm_hyb<1, 4><<<dim3(Tdim / 128, Hdim / 128), 512, SMEM>>>(
        hq, (const signed char*)hq_t, wqd, (const signed char*)wqd_t,
        wqd, (const signed char*)wqd_t, out, Idim, Idim / 128, Hdim, hinv, 2, 2);
}